// round 2
// baseline (speedup 1.0000x reference)
#include <cuda_runtime.h>

// x: (16, 256, 128, 128) fp32 -> 2x2 block sum * 0.5, then 2x2 NN upsample.
//
// Each thread handles one row pair x TWO adjacent float4 columns (8 w-elems):
//   4 x LDG.128 (front-batched, MLP=4) + 4 x STG.128, all with streaming
//   (.cs) cache hints since the 537 MB working set flows through L2 once.
//
// Row = 128 floats = 32 float4. Thread covers cols [2c, 2c+1] of rows
// [2r, 2r+1]. 16*256*64 row pairs x 16 col-chunks = 4,194,304 threads.

__global__ void __launch_bounds__(256) wfdm_kernel(
    const float4* __restrict__ in, float4* __restrict__ out)
{
    int tid = blockIdx.x * blockDim.x + threadIdx.x;

    int chunk   = tid & 15;        // which pair of float4s in the row (0..15)
    int rowpair = tid >> 4;        // which pair of rows

    // row stride = 32 float4; row pair spans 64 float4
    int base = rowpair * 64 + chunk * 2;

    // Front-batched independent loads: MLP = 4
    float4 t0 = __ldcs(&in[base]);        // top row, first float4
    float4 t1 = __ldcs(&in[base + 1]);    // top row, second float4
    float4 b0 = __ldcs(&in[base + 32]);   // bottom row, first float4
    float4 b1 = __ldcs(&in[base + 33]);   // bottom row, second float4

    float s0 = (t0.x + t0.y + b0.x + b0.y) * 0.5f;
    float s1 = (t0.z + t0.w + b0.z + b0.w) * 0.5f;
    float s2 = (t1.x + t1.y + b1.x + b1.y) * 0.5f;
    float s3 = (t1.z + t1.w + b1.z + b1.w) * 0.5f;

    float4 o0 = make_float4(s0, s0, s1, s1);
    float4 o1 = make_float4(s2, s2, s3, s3);

    __stcs(&out[base],      o0);
    __stcs(&out[base + 1],  o1);
    __stcs(&out[base + 32], o0);
    __stcs(&out[base + 33], o1);
}

extern "C" void kernel_launch(void* const* d_in, const int* in_sizes, int n_in,
                              void* d_out, int out_size)
{
    const float4* in = (const float4*)d_in[0];
    float4* out = (float4*)d_out;

    // total threads = elements / 16 (each thread covers 16 floats)
    int total = out_size / 16;   // 16*256*128*128 / 16 = 4,194,304
    int threads = 256;
    int blocks = total / threads;  // exact: 16384
    wfdm_kernel<<<blocks, threads>>>(in, out);
}

// round 3
// speedup vs baseline: 1.0226x; 1.0226x over previous
#include <cuda_runtime.h>

// x: (16, 256, 128, 128) fp32 -> 2x2 block sum * 0.5, then 2x2 NN upsample.
//
// Each thread: ONE float4 column slot (lane-contiguous -> perfectly coalesced
// 128B warp accesses) x TWO row pairs (4 consecutive rows). 4 front-batched
// LDG.128 (MLP=4) + 4 STG.128.
//
// Row = 128 floats = 32 float4. Group g covers rows [4g, 4g+3].
// 16*256*32 groups x 32 col slots = 4,194,304 threads.

__global__ void __launch_bounds__(256) wfdm_kernel(
    const float4* __restrict__ in, float4* __restrict__ out)
{
    int tid = blockIdx.x * blockDim.x + threadIdx.x;

    int col   = tid & 31;      // float4 slot within row (0..31), lane-contiguous
    int group = tid >> 5;      // group of 4 rows (2 row pairs)

    int base = group * 128 + col;   // 4 rows * 32 float4/row

    // Front-batched independent loads, all lane-stride-1: MLP = 4
    float4 t0 = in[base];         // row 4g
    float4 b0 = in[base + 32];    // row 4g+1
    float4 t1 = in[base + 64];    // row 4g+2
    float4 b1 = in[base + 96];    // row 4g+3

    // Row pair 0
    float s0 = (t0.x + t0.y + b0.x + b0.y) * 0.5f;
    float s1 = (t0.z + t0.w + b0.z + b0.w) * 0.5f;
    // Row pair 1
    float s2 = (t1.x + t1.y + b1.x + b1.y) * 0.5f;
    float s3 = (t1.z + t1.w + b1.z + b1.w) * 0.5f;

    float4 o0 = make_float4(s0, s0, s1, s1);
    float4 o1 = make_float4(s2, s2, s3, s3);

    out[base]      = o0;
    out[base + 32] = o0;
    out[base + 64] = o1;
    out[base + 96] = o1;
}

extern "C" void kernel_launch(void* const* d_in, const int* in_sizes, int n_in,
                              void* d_out, int out_size)
{
    const float4* in = (const float4*)d_in[0];
    float4* out = (float4*)d_out;

    // total threads = elements / 16 (each thread covers 16 floats)
    int total = out_size / 16;   // 16*256*128*128 / 16 = 4,194,304
    int threads = 256;
    int blocks = total / threads;  // exact: 16384
    wfdm_kernel<<<blocks, threads>>>(in, out);
}

// round 4
// speedup vs baseline: 1.0242x; 1.0016x over previous
#include <cuda_runtime.h>

// x: (16, 256, 128, 128) fp32 -> 2x2 block sum * 0.5, then 2x2 NN upsample.
//
// R3 layout (known-good coalescing): each thread owns ONE float4 column slot
// (lane-contiguous -> perfect 512B/warp accesses) x TWO row pairs (4
// consecutive rows). 4 front-batched LDG.128 + 4 STG.128.
//
// R4 change (single variable): streaming cache hints (.cs) on all loads and
// stores — 537 MB flows through the 126 MB L2 exactly once, so evict-first
// avoids filling L2 with dead lines and promotes prompt, stream-ordered
// writebacks.

__global__ void __launch_bounds__(256) wfdm_kernel(
    const float4* __restrict__ in, float4* __restrict__ out)
{
    int tid = blockIdx.x * blockDim.x + threadIdx.x;

    int col   = tid & 31;      // float4 slot within row (0..31), lane-contiguous
    int group = tid >> 5;      // group of 4 rows (2 row pairs)

    int base = group * 128 + col;   // 4 rows * 32 float4/row

    // Front-batched independent loads, all lane-stride-1: MLP = 4
    float4 t0 = __ldcs(&in[base]);         // row 4g
    float4 b0 = __ldcs(&in[base + 32]);    // row 4g+1
    float4 t1 = __ldcs(&in[base + 64]);    // row 4g+2
    float4 b1 = __ldcs(&in[base + 96]);    // row 4g+3

    // Row pair 0
    float s0 = (t0.x + t0.y + b0.x + b0.y) * 0.5f;
    float s1 = (t0.z + t0.w + b0.z + b0.w) * 0.5f;
    // Row pair 1
    float s2 = (t1.x + t1.y + b1.x + b1.y) * 0.5f;
    float s3 = (t1.z + t1.w + b1.z + b1.w) * 0.5f;

    float4 o0 = make_float4(s0, s0, s1, s1);
    float4 o1 = make_float4(s2, s2, s3, s3);

    __stcs(&out[base],      o0);
    __stcs(&out[base + 32], o0);
    __stcs(&out[base + 64], o1);
    __stcs(&out[base + 96], o1);
}

extern "C" void kernel_launch(void* const* d_in, const int* in_sizes, int n_in,
                              void* d_out, int out_size)
{
    const float4* in = (const float4*)d_in[0];
    float4* out = (float4*)d_out;

    // total threads = elements / 16 (each thread covers 16 floats)
    int total = out_size / 16;   // 16*256*128*128 / 16 = 4,194,304
    int threads = 256;
    int blocks = total / threads;  // exact: 16384
    wfdm_kernel<<<blocks, threads>>>(in, out);
}